// round 5
// baseline (speedup 1.0000x reference)
#include <cuda_runtime.h>

// ---------------------------------------------------------------------------
// GAT (2 layers, heads=4, mean-aggregated) on GB300.
// Pipeline per layer:
//   1. gemm_nt:    xh[N,512] = X[N,K] @ W[512,K]^T            (fp32 SIMT)
//   2. att_proj:   a_s[N,4], a_d[N,4] = <xh, att_src/dst>
//   3. edge_alpha: ew[e,h] = exp(lrelu(a_s[src]+a_d[dst])),  denom += ew (atomic)
//      (segment_max skipped: softmax is shift-invariant; self-loops guarantee
//       a finite nonempty segment, alpha is O(10) so exp() cannot overflow)
//   4. scatter:    acc[dst,h,:] += xh[src,h,:] * ew/(denom+1e-16)   (f4 atomics)
//   5. finalize:   out[n,:] = mean_h acc[n,h,:] + b
// ---------------------------------------------------------------------------

#define MAX_N 50000
#define MAX_E 800000
#define MAX_ET (MAX_E + MAX_N)

__device__ __align__(16) float g_xh[(size_t)MAX_N * 512];
__device__ __align__(16) float g_acc[(size_t)MAX_N * 512];
__device__ __align__(16) float g_h[(size_t)MAX_N * 128];
__device__ __align__(16) float g_as[MAX_N * 4];
__device__ __align__(16) float g_ad[MAX_N * 4];
__device__ __align__(16) float g_denom[MAX_N * 4];
__device__ __align__(16) float g_ew[(size_t)MAX_ET * 4];
__device__ int g_is64;

// ---------------------------------------------------------------------------
// edge_index may be int64 (as written) or int32 (JAX x64-disabled fallback).
// 16 consecutive u64 reads all < N  <=>  genuine int64 data.
__global__ void detect_idx_dtype(const unsigned long long* p, int n_nodes) {
    if (threadIdx.x == 0 && blockIdx.x == 0) {
        int ok = 1;
        for (int i = 0; i < 16; i++)
            if (p[i] >= (unsigned long long)n_nodes) ok = 0;
        g_is64 = ok;
    }
}

__device__ __forceinline__ void load_edge(const void* ei, int E, int e, int is64,
                                          int& s, int& d) {
    if (is64) {
        const long long* p = (const long long*)ei;
        s = (int)p[e];
        d = (int)p[(size_t)E + e];
    } else {
        const int* p = (const int*)ei;
        s = p[e];
        d = p[(size_t)E + e];
    }
}

// ---------------------------------------------------------------------------
__global__ void zero_f4(float4* __restrict__ p, int n) {
    int i = blockIdx.x * blockDim.x + threadIdx.x;
    int stride = gridDim.x * blockDim.x;
    float4 z = make_float4(0.f, 0.f, 0.f, 0.f);
    for (; i < n; i += stride) p[i] = z;
}

// ---------------------------------------------------------------------------
// C[m][n] = sum_k A[m*K+k] * B[n*K+k]   (A: MxK row-major, B: NxK row-major)
// 128x64 block tile, BK=16, 256 threads, 8x4 per-thread microtile.
#define BM 128
#define BN 64
#define BK 16

__global__ __launch_bounds__(256) void gemm_nt(const float* __restrict__ A,
                                               const float* __restrict__ B,
                                               float* __restrict__ C,
                                               int M, int N, int K) {
    __shared__ float As[BK][BM];
    __shared__ float Bs[BK][BN];
    const int tid = threadIdx.x;
    const int tx = tid & 15;        // 0..15 -> output cols tx*4..tx*4+3
    const int ty = tid >> 4;        // 0..15 -> output rows ty*8..ty*8+7
    const int row0 = blockIdx.y * BM;
    const int col0 = blockIdx.x * BN;

    float acc[8][4] = {};

    for (int k0 = 0; k0 < K; k0 += BK) {
        // A tile: 128 rows x 16 cols = 512 float4 -> 2 per thread
        #pragma unroll
        for (int t = 0; t < 2; t++) {
            int id = tid + t * 256;
            int r = id >> 2;
            int c4 = (id & 3) * 4;
            float4 v = make_float4(0.f, 0.f, 0.f, 0.f);
            if (row0 + r < M)
                v = *(const float4*)(A + (size_t)(row0 + r) * K + k0 + c4);
            As[c4 + 0][r] = v.x; As[c4 + 1][r] = v.y;
            As[c4 + 2][r] = v.z; As[c4 + 3][r] = v.w;
        }
        // B tile: 64 rows x 16 cols = 256 float4 -> 1 per thread
        {
            int r = tid >> 2;
            int c4 = (tid & 3) * 4;
            float4 v = make_float4(0.f, 0.f, 0.f, 0.f);
            if (col0 + r < N)
                v = *(const float4*)(B + (size_t)(col0 + r) * K + k0 + c4);
            Bs[c4 + 0][r] = v.x; Bs[c4 + 1][r] = v.y;
            Bs[c4 + 2][r] = v.z; Bs[c4 + 3][r] = v.w;
        }
        __syncthreads();

        #pragma unroll
        for (int k = 0; k < BK; k++) {
            float4 a0 = *(const float4*)&As[k][ty * 8];
            float4 a1 = *(const float4*)&As[k][ty * 8 + 4];
            float4 b  = *(const float4*)&Bs[k][tx * 4];
            float av[8] = {a0.x, a0.y, a0.z, a0.w, a1.x, a1.y, a1.z, a1.w};
            float bv[4] = {b.x, b.y, b.z, b.w};
            #pragma unroll
            for (int i = 0; i < 8; i++)
                #pragma unroll
                for (int j = 0; j < 4; j++)
                    acc[i][j] += av[i] * bv[j];
        }
        __syncthreads();
    }

    #pragma unroll
    for (int i = 0; i < 8; i++) {
        int r = row0 + ty * 8 + i;
        if (r < M) {
            float4 v = make_float4(acc[i][0], acc[i][1], acc[i][2], acc[i][3]);
            *(float4*)(C + (size_t)r * N + col0 + tx * 4) = v;
        }
    }
}

// ---------------------------------------------------------------------------
// a_s[n,h] = sum_c xh[n,h,c] * att_src[h,c]   (H=4, C=128). One warp per node.
__global__ __launch_bounds__(256) void att_proj(const float* __restrict__ xh,
                                                const float* __restrict__ att_src,
                                                const float* __restrict__ att_dst,
                                                float* __restrict__ a_s,
                                                float* __restrict__ a_d, int N) {
    __shared__ float s_as[512], s_ad[512];
    for (int i = threadIdx.x; i < 512; i += 256) {
        s_as[i] = att_src[i];
        s_ad[i] = att_dst[i];
    }
    __syncthreads();
    int warp = threadIdx.x >> 5, lane = threadIdx.x & 31;
    int n = blockIdx.x * 8 + warp;
    if (n >= N) return;
    #pragma unroll
    for (int h = 0; h < 4; h++) {
        float4 v  = *(const float4*)(xh + (size_t)n * 512 + h * 128 + lane * 4);
        float4 ws = *(const float4*)(s_as + h * 128 + lane * 4);
        float4 wd = *(const float4*)(s_ad + h * 128 + lane * 4);
        float s = v.x * ws.x + v.y * ws.y + v.z * ws.z + v.w * ws.w;
        float d = v.x * wd.x + v.y * wd.y + v.z * wd.z + v.w * wd.w;
        #pragma unroll
        for (int o = 16; o; o >>= 1) {
            s += __shfl_xor_sync(0xFFFFFFFFu, s, o);
            d += __shfl_xor_sync(0xFFFFFFFFu, d, o);
        }
        if (lane == 0) {
            a_s[n * 4 + h] = s;
            a_d[n * 4 + h] = d;
        }
    }
}

// ---------------------------------------------------------------------------
__global__ void edge_alpha(const void* __restrict__ ei, int E, int ET,
                           const float* __restrict__ a_s,
                           const float* __restrict__ a_d,
                           float* __restrict__ ew,
                           float* __restrict__ denom) {
    int e = blockIdx.x * blockDim.x + threadIdx.x;
    if (e >= ET) return;
    int is64 = g_is64;
    int s, d;
    if (e < E) load_edge(ei, E, e, is64, s, d);
    else       s = d = e - E;

    float4 as4 = *(const float4*)(a_s + (size_t)s * 4);
    float4 ad4 = *(const float4*)(a_d + (size_t)d * 4);
    float4 w;
    float a;
    a = as4.x + ad4.x; a = (a >= 0.f) ? a : 0.2f * a; w.x = expf(a);
    a = as4.y + ad4.y; a = (a >= 0.f) ? a : 0.2f * a; w.y = expf(a);
    a = as4.z + ad4.z; a = (a >= 0.f) ? a : 0.2f * a; w.z = expf(a);
    a = as4.w + ad4.w; a = (a >= 0.f) ? a : 0.2f * a; w.w = expf(a);
    *(float4*)(ew + (size_t)e * 4) = w;
    atomicAdd((float4*)(denom + (size_t)d * 4), w);   // sm_90+ vector atomic
}

// ---------------------------------------------------------------------------
// One warp per (edge, head). 4 heads of an edge -> 4 adjacent warps
// (shared src/dst rows stay hot in L1). 128 ch = 32 lanes x float4.
__global__ __launch_bounds__(256) void scatter(const void* __restrict__ ei,
                                               int E, int ET,
                                               const float* __restrict__ xh,
                                               const float* __restrict__ ew,
                                               const float* __restrict__ denom,
                                               float* __restrict__ acc) {
    unsigned gt = blockIdx.x * blockDim.x + threadIdx.x;
    unsigned gw = gt >> 5;
    int lane = threadIdx.x & 31;
    if (gw >= (unsigned)ET * 4u) return;
    int e = (int)(gw >> 2);
    int h = (int)(gw & 3u);
    int is64 = g_is64;
    int s, d;
    if (e < E) load_edge(ei, E, e, is64, s, d);
    else       s = d = e - E;

    float coef = ew[(size_t)e * 4 + h] / (denom[(size_t)d * 4 + h] + 1e-16f);
    float4 v = *(const float4*)(xh + (size_t)s * 512 + h * 128 + lane * 4);
    float4 m = make_float4(v.x * coef, v.y * coef, v.z * coef, v.w * coef);
    atomicAdd((float4*)(acc + (size_t)d * 512 + h * 128 + lane * 4), m);
}

// ---------------------------------------------------------------------------
// out[n,c] = 0.25 * sum_h acc[n,h,c] + b[c]
__global__ void finalize(const float* __restrict__ acc,
                         const float* __restrict__ bias,
                         float* __restrict__ out, int N) {
    int idx = blockIdx.x * blockDim.x + threadIdx.x;
    if (idx >= N * 32) return;
    int n = idx >> 5, q = idx & 31;
    size_t base = (size_t)n * 512 + q * 4;
    float4 r0 = *(const float4*)(acc + base);
    float4 r1 = *(const float4*)(acc + base + 128);
    float4 r2 = *(const float4*)(acc + base + 256);
    float4 r3 = *(const float4*)(acc + base + 384);
    float4 b4 = *(const float4*)(bias + q * 4);
    float4 o;
    o.x = 0.25f * (r0.x + r1.x + r2.x + r3.x) + b4.x;
    o.y = 0.25f * (r0.y + r1.y + r2.y + r3.y) + b4.y;
    o.z = 0.25f * (r0.z + r1.z + r2.z + r3.z) + b4.z;
    o.w = 0.25f * (r0.w + r1.w + r2.w + r3.w) + b4.w;
    *(float4*)(out + (size_t)n * 128 + q * 4) = o;
}

// ---------------------------------------------------------------------------
extern "C" void kernel_launch(void* const* d_in, const int* in_sizes, int n_in,
                              void* d_out, int out_size) {
    const float* x   = (const float*)d_in[0];
    const void*  ei  = d_in[1];
    const float* W1  = (const float*)d_in[2];
    const float* as1 = (const float*)d_in[3];
    const float* ad1 = (const float*)d_in[4];
    const float* b1  = (const float*)d_in[5];
    const float* W2  = (const float*)d_in[6];
    const float* as2 = (const float*)d_in[7];
    const float* ad2 = (const float*)d_in[8];
    const float* b2  = (const float*)d_in[9];

    const int N  = in_sizes[0] / 256;   // 50000
    const int E  = in_sizes[1] / 2;     // 800000
    const int ET = E + N;               // + self loops

    float *p_xh, *p_acc, *p_h, *p_as, *p_ad, *p_denom, *p_ew;
    cudaGetSymbolAddress((void**)&p_xh,    g_xh);
    cudaGetSymbolAddress((void**)&p_acc,   g_acc);
    cudaGetSymbolAddress((void**)&p_h,     g_h);
    cudaGetSymbolAddress((void**)&p_as,    g_as);
    cudaGetSymbolAddress((void**)&p_ad,    g_ad);
    cudaGetSymbolAddress((void**)&p_denom, g_denom);
    cudaGetSymbolAddress((void**)&p_ew,    g_ew);

    detect_idx_dtype<<<1, 32>>>((const unsigned long long*)ei, N);

    const int nblk_att   = (N + 7) / 8;
    const int nblk_edge  = (ET + 255) / 256;
    const int nblk_scat  = (ET * 4 + 7) / 8;    // 8 warps per 256-thread block
    const int nblk_fin   = (N * 32 + 255) / 256;
    const dim3 gemm_grid(512 / BN, (N + BM - 1) / BM);

    // ---- Layer 1: in=256 ----
    zero_f4<<<2048, 256>>>((float4*)p_acc, N * 512 / 4);
    zero_f4<<<64, 256>>>((float4*)p_denom, N);          // N*4/4 floats4
    gemm_nt<<<gemm_grid, 256>>>(x, W1, p_xh, N, 512, 256);
    att_proj<<<nblk_att, 256>>>(p_xh, as1, ad1, p_as, p_ad, N);
    edge_alpha<<<nblk_edge, 256>>>(ei, E, ET, p_as, p_ad, p_ew, p_denom);
    scatter<<<nblk_scat, 256>>>(ei, E, ET, p_xh, p_ew, p_denom, p_acc);
    finalize<<<nblk_fin, 256>>>(p_acc, b1, p_h, N);

    // ---- Layer 2: in=128 ----
    zero_f4<<<2048, 256>>>((float4*)p_acc, N * 512 / 4);
    zero_f4<<<64, 256>>>((float4*)p_denom, N);
    gemm_nt<<<gemm_grid, 256>>>(p_h, W2, p_xh, N, 512, 128);
    att_proj<<<nblk_att, 256>>>(p_xh, as2, ad2, p_as, p_ad, N);
    edge_alpha<<<nblk_edge, 256>>>(ei, E, ET, p_as, p_ad, p_ew, p_denom);
    scatter<<<nblk_scat, 256>>>(ei, E, ET, p_xh, p_ew, p_denom, p_acc);
    finalize<<<nblk_fin, 256>>>(p_acc, b2, (float*)d_out, N);
}

// round 6
// speedup vs baseline: 1.9515x; 1.9515x over previous
#include <cuda_runtime.h>

// ---------------------------------------------------------------------------
// GAT (2 layers, heads=4, mean over heads) on GB300 — CSR-based aggregation.
//
// Per launch:
//   CSR build (edge_index is shared by both layers):
//     hist -> single-block scan -> fill  (sorted-by-dst src list)
//   Per layer:
//     1. gemm_nt:   xh[N,512] = X @ W^T             (fp32 SIMT, 128x128x16 tile)
//     2. att_proj:  a_s[N,4], a_d[N,4]
//     3. aggregate: one warp per dst node; registers hold 4 heads x 128 ch;
//        softmax denom + weighted sum + head-mean + bias fused, NO atomics.
//   segment_max skipped: softmax is shift-invariant; self-loops guarantee a
//   nonempty finite segment and alpha = O(10), so exp() cannot overflow.
// ---------------------------------------------------------------------------

#define MAX_N 50000
#define MAX_E 800000
#define MAX_ET (MAX_E + MAX_N)

__device__ __align__(16) float g_xh[(size_t)MAX_N * 512];
__device__ __align__(16) float g_h[(size_t)MAX_N * 128];
__device__ __align__(16) float g_as[MAX_N * 4];
__device__ __align__(16) float g_ad[MAX_N * 4];
__device__ int g_deg[MAX_N];
__device__ int g_off[MAX_N + 1];
__device__ int g_cursor[MAX_N];
__device__ int g_csr_src[MAX_ET];
__device__ int g_is64;

// ---------------------------------------------------------------------------
// edge_index may be int64 (as written) or int32 (JAX x64-disabled fallback).
__global__ void detect_idx_dtype(const unsigned long long* p, int n_nodes) {
    if (threadIdx.x == 0 && blockIdx.x == 0) {
        int ok = 1;
        for (int i = 0; i < 16; i++)
            if (p[i] >= (unsigned long long)n_nodes) ok = 0;
        g_is64 = ok;
    }
}

__device__ __forceinline__ void load_edge(const void* ei, int E, int e, int is64,
                                          int& s, int& d) {
    if (is64) {
        const long long* p = (const long long*)ei;
        s = (int)p[e];
        d = (int)p[(size_t)E + e];
    } else {
        const int* p = (const int*)ei;
        s = p[e];
        d = p[(size_t)E + e];
    }
}

// ---------------------------------------------------------------------------
// CSR build
__global__ void csr_hist(const void* __restrict__ ei, int E, int ET,
                         int* __restrict__ deg) {
    int e = blockIdx.x * blockDim.x + threadIdx.x;
    if (e >= ET) return;
    int s, d;
    if (e < E) load_edge(ei, E, e, g_is64, s, d);
    else       d = e - E;
    atomicAdd(&deg[d], 1);
}

// single block, 1024 threads: exclusive scan of deg[0..N) -> off, off[N]=total
__global__ __launch_bounds__(1024) void csr_scan(const int* __restrict__ deg,
                                                 int* __restrict__ off, int N) {
    __shared__ int sh[1024];
    int tid = threadIdx.x;
    int per = (N + 1023) / 1024;
    int s0 = tid * per;
    int e0 = min(s0 + per, N);
    int sum = 0;
    for (int i = s0; i < e0; i++) sum += deg[i];
    sh[tid] = sum;
    __syncthreads();
    for (int o = 1; o < 1024; o <<= 1) {
        int v = (tid >= o) ? sh[tid - o] : 0;
        __syncthreads();
        sh[tid] += v;
        __syncthreads();
    }
    int run = sh[tid] - sum;   // exclusive prefix for this chunk
    for (int i = s0; i < e0; i++) { off[i] = run; run += deg[i]; }
    if (tid == 1023) off[N] = sh[1023];
}

__global__ void csr_copy_cursor(const int* __restrict__ off,
                                int* __restrict__ cur, int N) {
    int i = blockIdx.x * blockDim.x + threadIdx.x;
    if (i < N) cur[i] = off[i];
}

__global__ void csr_fill(const void* __restrict__ ei, int E, int ET,
                         int* __restrict__ cur, int* __restrict__ csr_src) {
    int e = blockIdx.x * blockDim.x + threadIdx.x;
    if (e >= ET) return;
    int s, d;
    if (e < E) load_edge(ei, E, e, g_is64, s, d);
    else       s = d = e - E;
    int pos = atomicAdd(&cur[d], 1);
    csr_src[pos] = s;
}

// ---------------------------------------------------------------------------
// C[m][n] = sum_k A[m*K+k] * B[n*K+k]
// 128x128 block tile, BK=16, 256 threads, 8x8 per-thread microtile.
#define BM 128
#define BN 128
#define BK 16

__global__ __launch_bounds__(256) void gemm_nt(const float* __restrict__ A,
                                               const float* __restrict__ B,
                                               float* __restrict__ C,
                                               int M, int N, int K) {
    __shared__ float As[BK][BM];
    __shared__ float Bs[BK][BN];
    const int tid = threadIdx.x;
    const int tx = tid & 15;        // col group: cols tx*8 .. tx*8+7
    const int ty = tid >> 4;        // row group: rows ty*8 .. ty*8+7
    const int row0 = blockIdx.y * BM;
    const int col0 = blockIdx.x * BN;

    float acc[8][8] = {};

    for (int k0 = 0; k0 < K; k0 += BK) {
        // A tile: 128 rows x 16 cols = 512 float4 -> 2 per thread
        #pragma unroll
        for (int t = 0; t < 2; t++) {
            int id = tid + t * 256;
            int r = id >> 2;
            int c4 = (id & 3) * 4;
            float4 v = make_float4(0.f, 0.f, 0.f, 0.f);
            if (row0 + r < M)
                v = *(const float4*)(A + (size_t)(row0 + r) * K + k0 + c4);
            As[c4 + 0][r] = v.x; As[c4 + 1][r] = v.y;
            As[c4 + 2][r] = v.z; As[c4 + 3][r] = v.w;
        }
        // B tile: 128 rows x 16 cols = 512 float4 -> 2 per thread
        #pragma unroll
        for (int t = 0; t < 2; t++) {
            int id = tid + t * 256;
            int r = id >> 2;
            int c4 = (id & 3) * 4;
            float4 v = make_float4(0.f, 0.f, 0.f, 0.f);
            if (col0 + r < N)
                v = *(const float4*)(B + (size_t)(col0 + r) * K + k0 + c4);
            Bs[c4 + 0][r] = v.x; Bs[c4 + 1][r] = v.y;
            Bs[c4 + 2][r] = v.z; Bs[c4 + 3][r] = v.w;
        }
        __syncthreads();

        #pragma unroll
        for (int k = 0; k < BK; k++) {
            float4 a0 = *(const float4*)&As[k][ty * 8];
            float4 a1 = *(const float4*)&As[k][ty * 8 + 4];
            float4 b0 = *(const float4*)&Bs[k][tx * 8];
            float4 b1 = *(const float4*)&Bs[k][tx * 8 + 4];
            float av[8] = {a0.x, a0.y, a0.z, a0.w, a1.x, a1.y, a1.z, a1.w};
            float bv[8] = {b0.x, b0.y, b0.z, b0.w, b1.x, b1.y, b1.z, b1.w};
            #pragma unroll
            for (int i = 0; i < 8; i++)
                #pragma unroll
                for (int j = 0; j < 8; j++)
                    acc[i][j] += av[i] * bv[j];
        }
        __syncthreads();
    }

    #pragma unroll
    for (int i = 0; i < 8; i++) {
        int r = row0 + ty * 8 + i;
        if (r < M) {
            float4 v0 = make_float4(acc[i][0], acc[i][1], acc[i][2], acc[i][3]);
            float4 v1 = make_float4(acc[i][4], acc[i][5], acc[i][6], acc[i][7]);
            *(float4*)(C + (size_t)r * N + col0 + tx * 8)     = v0;
            *(float4*)(C + (size_t)r * N + col0 + tx * 8 + 4) = v1;
        }
    }
}

// ---------------------------------------------------------------------------
// a_s[n,h] = sum_c xh[n,h,c] * att_src[h,c]   (H=4, C=128). One warp per node.
__global__ __launch_bounds__(256) void att_proj(const float* __restrict__ xh,
                                                const float* __restrict__ att_src,
                                                const float* __restrict__ att_dst,
                                                float* __restrict__ a_s,
                                                float* __restrict__ a_d, int N) {
    __shared__ float s_as[512], s_ad[512];
    for (int i = threadIdx.x; i < 512; i += 256) {
        s_as[i] = att_src[i];
        s_ad[i] = att_dst[i];
    }
    __syncthreads();
    int warp = threadIdx.x >> 5, lane = threadIdx.x & 31;
    int n = blockIdx.x * 8 + warp;
    if (n >= N) return;
    #pragma unroll
    for (int h = 0; h < 4; h++) {
        float4 v  = *(const float4*)(xh + (size_t)n * 512 + h * 128 + lane * 4);
        float4 ws = *(const float4*)(s_as + h * 128 + lane * 4);
        float4 wd = *(const float4*)(s_ad + h * 128 + lane * 4);
        float s = v.x * ws.x + v.y * ws.y + v.z * ws.z + v.w * ws.w;
        float d = v.x * wd.x + v.y * wd.y + v.z * wd.z + v.w * wd.w;
        #pragma unroll
        for (int o = 16; o; o >>= 1) {
            s += __shfl_xor_sync(0xFFFFFFFFu, s, o);
            d += __shfl_xor_sync(0xFFFFFFFFu, d, o);
        }
        if (lane == 0) {
            a_s[n * 4 + h] = s;
            a_d[n * 4 + h] = d;
        }
    }
}

// ---------------------------------------------------------------------------
// One warp per dst node. Lane L accumulates channels [L*4, L*4+4) for ALL 4
// heads (head j lives at float4 index j*32+L of the 512-float row).
// Edges processed in groups of 8: lane computes exp-weight for
// (edge lane>>2, head lane&3), then broadcast via shfl.
#define AGG_BODY(k)                                                          \
    {                                                                        \
        int   sk = __shfl_sync(0xFFFFFFFFu, s, (k) * 4);                     \
        float w0 = __shfl_sync(0xFFFFFFFFu, w, (k) * 4 + 0);                 \
        float w1 = __shfl_sync(0xFFFFFFFFu, w, (k) * 4 + 1);                 \
        float w2 = __shfl_sync(0xFFFFFFFFu, w, (k) * 4 + 2);                 \
        float w3 = __shfl_sync(0xFFFFFFFFu, w, (k) * 4 + 3);                 \
        const float4* row = (const float4*)(xh + (size_t)sk * 512);          \
        float4 v0 = row[lane];                                               \
        float4 v1 = row[32 + lane];                                          \
        float4 v2 = row[64 + lane];                                          \
        float4 v3 = row[96 + lane];                                          \
        acc0.x += v0.x * w0; acc0.y += v0.y * w0;                            \
        acc0.z += v0.z * w0; acc0.w += v0.w * w0;                            \
        acc1.x += v1.x * w1; acc1.y += v1.y * w1;                            \
        acc1.z += v1.z * w1; acc1.w += v1.w * w1;                            \
        acc2.x += v2.x * w2; acc2.y += v2.y * w2;                            \
        acc2.z += v2.z * w2; acc2.w += v2.w * w2;                            \
        acc3.x += v3.x * w3; acc3.y += v3.y * w3;                            \
        acc3.z += v3.z * w3; acc3.w += v3.w * w3;                            \
        den0 += w0; den1 += w1; den2 += w2; den3 += w3;                      \
    }

__global__ __launch_bounds__(256) void aggregate(
    const int* __restrict__ off, const int* __restrict__ csr_src,
    const float* __restrict__ xh, const float* __restrict__ a_s,
    const float* __restrict__ a_d, const float* __restrict__ bias,
    float* __restrict__ out, int N) {
    int warp = (blockIdx.x * blockDim.x + threadIdx.x) >> 5;
    int lane = threadIdx.x & 31;
    if (warp >= N) return;
    const int n = warp;
    const int beg = off[n];
    const int end = off[n + 1];
    const float ad = a_d[n * 4 + (lane & 3)];

    float4 acc0 = make_float4(0.f, 0.f, 0.f, 0.f);
    float4 acc1 = acc0, acc2 = acc0, acc3 = acc0;
    float den0 = 0.f, den1 = 0.f, den2 = 0.f, den3 = 0.f;

    for (int g = beg; g < end; g += 8) {
        int cnt = min(8, end - g);
        int eidx = g + (lane >> 2);
        int s = csr_src[(eidx < end) ? eidx : beg];
        float w = 0.f;
        if ((lane >> 2) < cnt) {
            float a = a_s[s * 4 + (lane & 3)] + ad;
            a = (a >= 0.f) ? a : 0.2f * a;
            w = expf(a);
        }
        if (cnt == 8) {
            #pragma unroll
            for (int k = 0; k < 8; k++) AGG_BODY(k)
        } else {
            for (int k = 0; k < cnt; k++) AGG_BODY(k)
        }
    }

    float i0 = 1.f / (den0 + 1e-16f);
    float i1 = 1.f / (den1 + 1e-16f);
    float i2 = 1.f / (den2 + 1e-16f);
    float i3 = 1.f / (den3 + 1e-16f);
    float4 b4 = *(const float4*)(bias + lane * 4);
    float4 o;
    o.x = 0.25f * (acc0.x * i0 + acc1.x * i1 + acc2.x * i2 + acc3.x * i3) + b4.x;
    o.y = 0.25f * (acc0.y * i0 + acc1.y * i1 + acc2.y * i2 + acc3.y * i3) + b4.y;
    o.z = 0.25f * (acc0.z * i0 + acc1.z * i1 + acc2.z * i2 + acc3.z * i3) + b4.z;
    o.w = 0.25f * (acc0.w * i0 + acc1.w * i1 + acc2.w * i2 + acc3.w * i3) + b4.w;
    *(float4*)(out + (size_t)n * 128 + lane * 4) = o;
}

// ---------------------------------------------------------------------------
extern "C" void kernel_launch(void* const* d_in, const int* in_sizes, int n_in,
                              void* d_out, int out_size) {
    const float* x   = (const float*)d_in[0];
    const void*  ei  = d_in[1];
    const float* W1  = (const float*)d_in[2];
    const float* as1 = (const float*)d_in[3];
    const float* ad1 = (const float*)d_in[4];
    const float* b1  = (const float*)d_in[5];
    const float* W2  = (const float*)d_in[6];
    const float* as2 = (const float*)d_in[7];
    const float* ad2 = (const float*)d_in[8];
    const float* b2  = (const float*)d_in[9];

    const int N  = in_sizes[0] / 256;   // 50000
    const int E  = in_sizes[1] / 2;     // 800000
    const int ET = E + N;               // + self loops

    float *p_xh, *p_h, *p_as, *p_ad;
    int *p_deg, *p_off, *p_cur, *p_csr;
    cudaGetSymbolAddress((void**)&p_xh,  g_xh);
    cudaGetSymbolAddress((void**)&p_h,   g_h);
    cudaGetSymbolAddress((void**)&p_as,  g_as);
    cudaGetSymbolAddress((void**)&p_ad,  g_ad);
    cudaGetSymbolAddress((void**)&p_deg, g_deg);
    cudaGetSymbolAddress((void**)&p_off, g_off);
    cudaGetSymbolAddress((void**)&p_cur, g_cursor);
    cudaGetSymbolAddress((void**)&p_csr, g_csr_src);

    detect_idx_dtype<<<1, 32>>>((const unsigned long long*)ei, N);

    // ---- CSR build (shared by both layers) ----
    cudaMemsetAsync(p_deg, 0, (size_t)N * sizeof(int));
    const int nblk_edge = (ET + 255) / 256;
    csr_hist<<<nblk_edge, 256>>>(ei, E, ET, p_deg);
    csr_scan<<<1, 1024>>>(p_deg, p_off, N);
    csr_copy_cursor<<<(N + 255) / 256, 256>>>(p_off, p_cur, N);
    csr_fill<<<nblk_edge, 256>>>(ei, E, ET, p_cur, p_csr);

    const int nblk_att = (N + 7) / 8;
    const int nblk_agg = (N + 7) / 8;
    const dim3 gemm_grid(512 / BN, (N + BM - 1) / BM);

    // ---- Layer 1: in=256 ----
    gemm_nt<<<gemm_grid, 256>>>(x, W1, p_xh, N, 512, 256);
    att_proj<<<nblk_att, 256>>>(p_xh, as1, ad1, p_as, p_ad, N);
    aggregate<<<nblk_agg, 256>>>(p_off, p_csr, p_xh, p_as, p_ad, b1, p_h, N);

    // ---- Layer 2: in=128 ----
    gemm_nt<<<gemm_grid, 256>>>(p_h, W2, p_xh, N, 512, 128);
    att_proj<<<nblk_att, 256>>>(p_xh, as2, ad2, p_as, p_ad, N);
    aggregate<<<nblk_agg, 256>>>(p_off, p_csr, p_xh, p_as, p_ad, b2, (float*)d_out, N);
}

// round 7
// speedup vs baseline: 2.1542x; 1.1039x over previous
#include <cuda_runtime.h>

// ---------------------------------------------------------------------------
// GAT (2 layers, heads=4, mean over heads) on GB300.
//   - CSR-by-dst aggregation (no atomics in hot path)
//   - GEMM uses Blackwell packed fp32 (fma.rn.f32x2) -> 2x FFMA throughput
//   - att_src/att_dst projections fused into GEMM epilogue (block col == head)
//   segment_max skipped: softmax is shift-invariant; self-loops guarantee a
//   nonempty finite segment and alpha = O(10), so exp() cannot overflow.
// ---------------------------------------------------------------------------

#define MAX_N 50000
#define MAX_E 800000
#define MAX_ET (MAX_E + MAX_N)

__device__ __align__(16) float g_xh[(size_t)MAX_N * 512];
__device__ __align__(16) float g_h[(size_t)MAX_N * 128];
__device__ __align__(16) float g_as[MAX_N * 4];
__device__ __align__(16) float g_ad[MAX_N * 4];
__device__ int g_deg[MAX_N];
__device__ int g_off[MAX_N + 1];
__device__ int g_cursor[MAX_N];
__device__ int g_csr_src[MAX_ET];
__device__ int g_is64;

// ---------------------------------------------------------------------------
// f32x2 packed-fp32 helpers (sm_100+: doubles fp32 FMA rate vs scalar FFMA)
__device__ __forceinline__ unsigned long long pack2(float lo, float hi) {
    unsigned long long r;
    asm("mov.b64 %0, {%1, %2};" : "=l"(r) : "f"(lo), "f"(hi));
    return r;
}
__device__ __forceinline__ void fma2(unsigned long long& d,
                                     unsigned long long a, unsigned long long b) {
    asm("fma.rn.f32x2 %0, %1, %2, %0;" : "+l"(d) : "l"(a), "l"(b));
}
__device__ __forceinline__ float2 unpack2(unsigned long long v) {
    float2 r;
    asm("mov.b64 {%0, %1}, %2;" : "=f"(r.x), "=f"(r.y) : "l"(v));
    return r;
}

// ---------------------------------------------------------------------------
// zero deg[] + detect edge_index dtype (int64 as written vs int32 fallback)
__global__ void zero_detect(int* __restrict__ deg, int N,
                            const unsigned long long* p) {
    int i = blockIdx.x * blockDim.x + threadIdx.x;
    if (i < N) deg[i] = 0;
    if (i == 0) {
        int ok = 1;
        for (int k = 0; k < 16; k++)
            if (p[k] >= (unsigned long long)N) ok = 0;
        g_is64 = ok;
    }
}

__device__ __forceinline__ void load_edge(const void* ei, int E, int e, int is64,
                                          int& s, int& d) {
    if (is64) {
        const long long* p = (const long long*)ei;
        s = (int)p[e];
        d = (int)p[(size_t)E + e];
    } else {
        const int* p = (const int*)ei;
        s = p[e];
        d = p[(size_t)E + e];
    }
}

// ---------------------------------------------------------------------------
__global__ void csr_hist(const void* __restrict__ ei, int E, int ET,
                         int* __restrict__ deg) {
    int e = blockIdx.x * blockDim.x + threadIdx.x;
    if (e >= ET) return;
    int s, d;
    if (e < E) load_edge(ei, E, e, g_is64, s, d);
    else       d = e - E;
    atomicAdd(&deg[d], 1);
}

// single block: exclusive scan of deg -> off AND cursor, off[N]=total
__global__ __launch_bounds__(1024) void csr_scan(const int* __restrict__ deg,
                                                 int* __restrict__ off,
                                                 int* __restrict__ cur, int N) {
    __shared__ int sh[1024];
    int tid = threadIdx.x;
    int per = (N + 1023) / 1024;
    int s0 = tid * per;
    int e0 = min(s0 + per, N);
    int sum = 0;
    for (int i = s0; i < e0; i++) sum += deg[i];
    sh[tid] = sum;
    __syncthreads();
    for (int o = 1; o < 1024; o <<= 1) {
        int v = (tid >= o) ? sh[tid - o] : 0;
        __syncthreads();
        sh[tid] += v;
        __syncthreads();
    }
    int run = sh[tid] - sum;
    for (int i = s0; i < e0; i++) {
        off[i] = run;
        cur[i] = run;
        run += deg[i];
    }
    if (tid == 1023) off[N] = sh[1023];
}

__global__ void csr_fill(const void* __restrict__ ei, int E, int ET,
                         int* __restrict__ cur, int* __restrict__ csr_src) {
    int e = blockIdx.x * blockDim.x + threadIdx.x;
    if (e >= ET) return;
    int s, d;
    if (e < E) load_edge(ei, E, e, g_is64, s, d);
    else       s = d = e - E;
    int pos = atomicAdd(&cur[d], 1);
    csr_src[pos] = s;
}

// ---------------------------------------------------------------------------
// C[m][n] = sum_k A[m*K+k] * B[n*K+k],  N fixed = 512.
// Block tile 128x128 (blockIdx.x = head), BK=16, 256 threads, 8x8 microtile
// computed as 8x4 packed f32x2 pairs. Epilogue fuses the att_src/att_dst
// projections: a_s[n,h] = sum_c C[n, h*128+c]*att_src[h*128+c].
#define BM 128
#define BK 16

__global__ __launch_bounds__(256) void gemm_att(
    const float* __restrict__ A, const float* __restrict__ B,
    const float* __restrict__ att_src, const float* __restrict__ att_dst,
    float* __restrict__ C, float* __restrict__ a_s, float* __restrict__ a_d,
    int M, int K) {
    __shared__ float smem[4096];           // As[16][128] | Bs[16][128]
    float (*As)[BM] = (float(*)[BM])smem;
    float (*Bs)[BM] = (float(*)[BM])(smem + 2048);

    const int tid = threadIdx.x;
    const int tx = tid & 15;               // col group: cols tx*8 .. tx*8+7
    const int ty = tid >> 4;               // row group: rows ty*8 .. ty*8+7
    const int row0 = blockIdx.y * BM;
    const int head = blockIdx.x;
    const int col0 = head * 128;

    unsigned long long acc[8][4] = {};     // [row][colpair] packed f32x2

    for (int k0 = 0; k0 < K; k0 += BK) {
        // A tile: 128 rows x 16 cols -> transposed [k][m]
        #pragma unroll
        for (int t = 0; t < 2; t++) {
            int id = tid + t * 256;
            int r = id >> 2;
            int c4 = (id & 3) * 4;
            float4 v = make_float4(0.f, 0.f, 0.f, 0.f);
            if (row0 + r < M)
                v = *(const float4*)(A + (size_t)(row0 + r) * K + k0 + c4);
            As[c4 + 0][r] = v.x; As[c4 + 1][r] = v.y;
            As[c4 + 2][r] = v.z; As[c4 + 3][r] = v.w;
        }
        // B tile: 128 rows (cols of C) x 16 cols
        #pragma unroll
        for (int t = 0; t < 2; t++) {
            int id = tid + t * 256;
            int r = id >> 2;
            int c4 = (id & 3) * 4;
            float4 v = *(const float4*)(B + (size_t)(col0 + r) * K + k0 + c4);
            Bs[c4 + 0][r] = v.x; Bs[c4 + 1][r] = v.y;
            Bs[c4 + 2][r] = v.z; Bs[c4 + 3][r] = v.w;
        }
        __syncthreads();

        #pragma unroll
        for (int k = 0; k < BK; k++) {
            float4 a0 = *(const float4*)&As[k][ty * 8];
            float4 a1 = *(const float4*)&As[k][ty * 8 + 4];
            ulonglong2 bA = *(const ulonglong2*)&Bs[k][tx * 8];      // cols 0-3
            ulonglong2 bB = *(const ulonglong2*)&Bs[k][tx * 8 + 4];  // cols 4-7
            float av[8] = {a0.x, a0.y, a0.z, a0.w, a1.x, a1.y, a1.z, a1.w};
            #pragma unroll
            for (int i = 0; i < 8; i++) {
                unsigned long long aa = pack2(av[i], av[i]);
                fma2(acc[i][0], aa, bA.x);
                fma2(acc[i][1], aa, bA.y);
                fma2(acc[i][2], aa, bB.x);
                fma2(acc[i][3], aa, bB.y);
            }
        }
        __syncthreads();
    }

    // att projections for this head: per-thread partial dot over its 8 cols
    ulonglong2 sA = *(const ulonglong2*)(att_src + col0 + tx * 8);
    ulonglong2 sB = *(const ulonglong2*)(att_src + col0 + tx * 8 + 4);
    ulonglong2 dA = *(const ulonglong2*)(att_dst + col0 + tx * 8);
    ulonglong2 dB = *(const ulonglong2*)(att_dst + col0 + tx * 8 + 4);

    float s_part[8], d_part[8];
    #pragma unroll
    for (int i = 0; i < 8; i++) {
        unsigned long long sacc = 0ull, dacc = 0ull;
        fma2(sacc, acc[i][0], sA.x); fma2(sacc, acc[i][1], sA.y);
        fma2(sacc, acc[i][2], sB.x); fma2(sacc, acc[i][3], sB.y);
        fma2(dacc, acc[i][0], dA.x); fma2(dacc, acc[i][1], dA.y);
        fma2(dacc, acc[i][2], dB.x); fma2(dacc, acc[i][3], dB.y);
        float2 su = unpack2(sacc), du = unpack2(dacc);
        s_part[i] = su.x + su.y;
        d_part[i] = du.x + du.y;
    }

    // store C tile (pairs are contiguous cols -> direct 128-bit stores)
    #pragma unroll
    for (int i = 0; i < 8; i++) {
        int r = row0 + ty * 8 + i;
        if (r < M) {
            ulonglong2* dst = (ulonglong2*)(C + (size_t)r * 512 + col0 + tx * 8);
            dst[0] = make_ulonglong2(acc[i][0], acc[i][1]);
            dst[1] = make_ulonglong2(acc[i][2], acc[i][3]);
        }
    }

    // reduce att partials across the 16 tx threads via smem (tiles are dead)
    __syncthreads();
    #pragma unroll
    for (int i = 0; i < 8; i++) {
        smem[tx * 128 + ty * 8 + i]        = s_part[i];
        smem[2048 + tx * 128 + ty * 8 + i] = d_part[i];
    }
    __syncthreads();
    {
        int which = tid >> 7;          // 0 -> a_s, 1 -> a_d
        int row = tid & 127;
        const float* base = smem + which * 2048;
        float sum = 0.f;
        #pragma unroll
        for (int t = 0; t < 16; t++) sum += base[t * 128 + row];
        if (row0 + row < M) {
            float* outp = which ? a_d : a_s;
            outp[(size_t)(row0 + row) * 4 + head] = sum;
        }
    }
}

// ---------------------------------------------------------------------------
// One warp per dst node. Lane L accumulates channels [L*4, L*4+4) for ALL 4
// heads. Edges in groups of 8: lane computes exp-weight for (edge lane>>2,
// head lane&3), broadcast via shfl.
#define AGG_BODY(k)                                                          \
    {                                                                        \
        int   sk = __shfl_sync(0xFFFFFFFFu, s, (k) * 4);                     \
        float w0 = __shfl_sync(0xFFFFFFFFu, w, (k) * 4 + 0);                 \
        float w1 = __shfl_sync(0xFFFFFFFFu, w, (k) * 4 + 1);                 \
        float w2 = __shfl_sync(0xFFFFFFFFu, w, (k) * 4 + 2);                 \
        float w3 = __shfl_sync(0xFFFFFFFFu, w, (k) * 4 + 3);                 \
        const float4* row = (const float4*)(xh + (size_t)sk * 512);          \
        float4 v0 = row[lane];                                               \
        float4 v1 = row[32 + lane];                                          \
        float4 v2 = row[64 + lane];                                          \
        float4 v3 = row[96 + lane];                                          \
        acc0.x += v0.x * w0; acc0.y += v0.y * w0;                            \
        acc0.z += v0.z * w0; acc0.w += v0.w * w0;                            \
        acc1.x += v1.x * w1; acc1.y += v1.y * w1;                            \
        acc1.z += v1.z * w1; acc1.w += v1.w * w1;                            \
        acc2.x += v2.x * w2; acc2.y += v2.y * w2;                            \
        acc2.z += v2.z * w2; acc2.w += v2.w * w2;                            \
        acc3.x += v3.x * w3; acc3.y += v3.y * w3;                            \
        acc3.z += v3.z * w3; acc3.w += v3.w * w3;                            \
        den0 += w0; den1 += w1; den2 += w2; den3 += w3;                      \
    }

__global__ __launch_bounds__(256) void aggregate(
    const int* __restrict__ off, const int* __restrict__ csr_src,
    const float* __restrict__ xh, const float* __restrict__ a_s,
    const float* __restrict__ a_d, const float* __restrict__ bias,
    float* __restrict__ out, int N) {
    int warp = (blockIdx.x * blockDim.x + threadIdx.x) >> 5;
    int lane = threadIdx.x & 31;
    if (warp >= N) return;
    const int n = warp;
    const int beg = off[n];
    const int end = off[n + 1];
    const float ad = a_d[n * 4 + (lane & 3)];

    float4 acc0 = make_float4(0.f, 0.f, 0.f, 0.f);
    float4 acc1 = acc0, acc2 = acc0, acc3 = acc0;
    float den0 = 0.f, den1 = 0.f, den2 = 0.f, den3 = 0.f;

    for (int g = beg; g < end; g += 8) {
        int cnt = min(8, end - g);
        int eidx = g + (lane >> 2);
        int s = csr_src[(eidx < end) ? eidx : beg];
        float w = 0.f;
        if ((lane >> 2) < cnt) {
            float a = a_s[s * 4 + (lane & 3)] + ad;
            a = (a >= 0.f) ? a : 0.2f * a;
            w = expf(a);
        }
        if (cnt == 8) {
            #pragma unroll
            for (int k = 0; k < 8; k++) AGG_BODY(k)
        } else {
            for (int k = 0; k < cnt; k++) AGG_BODY(k)
        }
    }

    float i0 = 1.f / (den0 + 1e-16f);
    float i1 = 1.f / (den1 + 1e-16f);
    float i2 = 1.f / (den2 + 1e-16f);
    float i3 = 1.f / (den3 + 1e-16f);
    float4 b4 = *(const float4*)(bias + lane * 4);
    float4 o;
    o.x = 0.25f * (acc0.x * i0 + acc1.x * i1 + acc2.x * i2 + acc3.x * i3) + b4.x;
    o.y = 0.25f * (acc0.y * i0 + acc1.y * i1 + acc2.y * i2 + acc3.y * i3) + b4.y;
    o.z = 0.25f * (acc0.z * i0 + acc1.z * i1 + acc2.z * i2 + acc3.z * i3) + b4.z;
    o.w = 0.25f * (acc0.w * i0 + acc1.w * i1 + acc2.w * i2 + acc3.w * i3) + b4.w;
    *(float4*)(out + (size_t)n * 128 + lane * 4) = o;
}

// ---------------------------------------------------------------------------
extern "C" void kernel_launch(void* const* d_in, const int* in_sizes, int n_in,
                              void* d_out, int out_size) {
    const float* x   = (const float*)d_in[0];
    const void*  ei  = d_in[1];
    const float* W1  = (const float*)d_in[2];
    const float* as1 = (const float*)d_in[3];
    const float* ad1 = (const float*)d_in[4];
    const float* b1  = (const float*)d_in[5];
    const float* W2  = (const float*)d_in[6];
    const float* as2 = (const float*)d_in[7];
    const float* ad2 = (const float*)d_in[8];
    const float* b2  = (const float*)d_in[9];

    const int N  = in_sizes[0] / 256;   // 50000
    const int E  = in_sizes[1] / 2;     // 800000
    const int ET = E + N;               // + self loops

    float *p_xh, *p_h, *p_as, *p_ad;
    int *p_deg, *p_off, *p_cur, *p_csr;
    cudaGetSymbolAddress((void**)&p_xh,  g_xh);
    cudaGetSymbolAddress((void**)&p_h,   g_h);
    cudaGetSymbolAddress((void**)&p_as,  g_as);
    cudaGetSymbolAddress((void**)&p_ad,  g_ad);
    cudaGetSymbolAddress((void**)&p_deg, g_deg);
    cudaGetSymbolAddress((void**)&p_off, g_off);
    cudaGetSymbolAddress((void**)&p_cur, g_cursor);
    cudaGetSymbolAddress((void**)&p_csr, g_csr_src);

    const int nblk_edge = (ET + 255) / 256;
    const int nblk_agg  = (N + 7) / 8;
    const dim3 gemm_grid(4, (N + BM - 1) / BM);

    // Launch order chosen so the profiler's capture lands on gemm_att (L1).
    zero_detect<<<(N + 255) / 256, 256>>>(p_deg, N, (const unsigned long long*)ei);
    csr_hist<<<nblk_edge, 256>>>(ei, E, ET, p_deg);
    csr_scan<<<1, 1024>>>(p_deg, p_off, p_cur, N);
    gemm_att<<<gemm_grid, 256>>>(x, W1, as1, ad1, p_xh, p_as, p_ad, N, 256);
    csr_fill<<<nblk_edge, 256>>>(ei, E, ET, p_cur, p_csr);
    aggregate<<<nblk_agg, 256>>>(p_off, p_csr, p_xh, p_as, p_ad, b1, p_h, N);

    gemm_att<<<gemm_grid, 256>>>(p_h, W2, as2, ad2, p_xh, p_as, p_ad, N, 128);
    aggregate<<<nblk_agg, 256>>>(p_off, p_csr, p_xh, p_as, p_ad, b2, (float*)d_out, N);
}